// round 1
// baseline (speedup 1.0000x reference)
#include <cuda_runtime.h>

#define HWN 4096
#define CCH 128
#define NB 2
#define NHEADS 4
#define HD 32
#define EPSGN 1e-5f
#define SMSCALE 0.17677669529663689f  // 1/sqrt(32)

// -------- scratch (device globals; no allocation allowed) --------
__device__ float g_scale[2][NB][CCH];      // [tensor(0=x,1=ctx)][b][ch]
__device__ float g_shift[2][NB][CCH];
__device__ float g_effW[NB][3][CCH][CCH];  // [b][m(q,k,v)][o][c]
__device__ float g_effB[NB][3][CCH];
__device__ float g_q[NB][CCH][HWN];
__device__ float g_k[NB][CCH][HWN];
__device__ float g_v[NB][CCH][HWN];
__device__ float g_ao[NB][CCH][HWN];

// =================== GroupNorm stats -> per-channel scale/shift ===================
__global__ void gn_stats_kernel(const float* __restrict__ x, const float* __restrict__ ctx,
                                const float* __restrict__ gq, const float* __restrict__ bq,
                                const float* __restrict__ gc, const float* __restrict__ bc) {
    int g = blockIdx.x, b = blockIdx.y, t = blockIdx.z;
    const float* src = (t == 0 ? x : ctx) + ((size_t)b * CCH + g * 4) * HWN;
    float s = 0.f, s2 = 0.f;
    for (int i = threadIdx.x; i < 4 * HWN; i += 256) {
        float v = src[i]; s += v; s2 += v * v;
    }
    __shared__ float r1[256], r2[256];
    r1[threadIdx.x] = s; r2[threadIdx.x] = s2;
    __syncthreads();
    for (int st = 128; st > 0; st >>= 1) {
        if (threadIdx.x < st) {
            r1[threadIdx.x] += r1[threadIdx.x + st];
            r2[threadIdx.x] += r2[threadIdx.x + st];
        }
        __syncthreads();
    }
    __shared__ float mean_s, rstd_s;
    if (threadIdx.x == 0) {
        float mean = r1[0] * (1.f / 16384.f);
        float var  = r2[0] * (1.f / 16384.f) - mean * mean;
        mean_s = mean;
        rstd_s = rsqrtf(var + EPSGN);
    }
    __syncthreads();
    if (threadIdx.x < 4) {
        int ch = g * 4 + threadIdx.x;
        float gam = (t == 0 ? gq : gc)[ch];
        float bet = (t == 0 ? bq : bc)[ch];
        float sc = rstd_s * gam;
        g_scale[t][b][ch] = sc;
        g_shift[t][b][ch] = bet - mean_s * sc;
    }
}

// =================== fold GN (and softmax scale for q) into weights ===================
__global__ void eff_weights_kernel(const float* __restrict__ Wq, const float* __restrict__ Wk,
                                   const float* __restrict__ Wv) {
    int o = blockIdx.x, m = blockIdx.y, b = blockIdx.z;
    int c = threadIdx.x;
    const float* W = (m == 0 ? Wq : m == 1 ? Wk : Wv);
    float w = W[o * CCH + c];
    float sc = 1.f, sh = 0.f;
    if (m == 0)      { sc = g_scale[0][b][c]; sh = g_shift[0][b][c]; }
    else if (m == 1) { sc = g_scale[1][b][c]; sh = g_shift[1][b][c]; }
    float e  = w * sc;
    float bb = w * sh;
    if (m == 0) { e *= SMSCALE; bb *= SMSCALE; }
    g_effW[b][m][o][c] = e;
    __shared__ float red[128];
    red[c] = bb;
    __syncthreads();
    for (int st = 64; st > 0; st >>= 1) {
        if (c < st) red[c] += red[c + st];
        __syncthreads();
    }
    if (c == 0) g_effB[b][m][o] = red[0];
}

// =================== fused GN+conv1x1 GEMM: out[o,s] = b_eff[o] + sum_c Weff[o,c]*in[c,s] ===================
__global__ void qkv_gemm_kernel(const float* __restrict__ x, const float* __restrict__ ctx) {
    int s0 = blockIdx.x * 64;
    int o0 = blockIdx.y * 64;
    int bm = blockIdx.z;
    int b = bm / 3, m = bm % 3;
    const float* in = (m == 0 ? x : ctx) + (size_t)b * CCH * HWN;
    float* out = (m == 0 ? &g_q[b][0][0] : m == 1 ? &g_k[b][0][0] : &g_v[b][0][0]);
    const float* W = &g_effW[b][m][0][0];

    __shared__ float Wt[32][68];   // [c][o], padded vs bank conflicts
    __shared__ float Xt[32][68];   // [c][s]
    int tid = threadIdx.x;
    int ty = tid >> 4, tx = tid & 15;
    float acc[4][4] = {};
    for (int cb = 0; cb < 4; cb++) {
#pragma unroll
        for (int r = 0; r < 8; r++) {
            int idx = tid + r * 256;
            int o = idx >> 5, c = idx & 31;
            Wt[c][o] = W[(o0 + o) * CCH + cb * 32 + c];
        }
#pragma unroll
        for (int r = 0; r < 2; r++) {
            int idx = tid + r * 256;
            int c = idx >> 4, f = idx & 15;
            float4 v = *(const float4*)(in + (size_t)(cb * 32 + c) * HWN + s0 + f * 4);
            *(float4*)&Xt[c][f * 4] = v;
        }
        __syncthreads();
#pragma unroll
        for (int c = 0; c < 32; c++) {
            float4 wv = *(float4*)&Wt[c][ty * 4];
            float4 xv = *(float4*)&Xt[c][tx * 4];
            float wa[4] = {wv.x, wv.y, wv.z, wv.w};
            float xa[4] = {xv.x, xv.y, xv.z, xv.w};
#pragma unroll
            for (int i = 0; i < 4; i++)
#pragma unroll
                for (int j = 0; j < 4; j++)
                    acc[i][j] += wa[i] * xa[j];
        }
        __syncthreads();
    }
#pragma unroll
    for (int i = 0; i < 4; i++) {
        int o = o0 + ty * 4 + i;
        float bias = g_effB[b][m][o];
        float4 v = {acc[i][0] + bias, acc[i][1] + bias, acc[i][2] + bias, acc[i][3] + bias};
        *(float4*)(out + (size_t)o * HWN + s0 + tx * 4) = v;
    }
}

// =================== flash attention, fp32, BM=BN=64, hd=32 ===================
__global__ void attn_kernel() {
    int dtile = blockIdx.x;
    int bh = blockIdx.y;
    int b = bh >> 2, n = bh & 3;
    const float* Q = &g_q[b][n * HD][0];
    const float* K = &g_k[b][n * HD][0];
    const float* V = &g_v[b][n * HD][0];

    __shared__ float Qs[HD][64];
    __shared__ float Ks[HD][64];
    __shared__ float Vs[HD][68];
    __shared__ float Ps[64][68];

    int tid = threadIdx.x;
    int ty = tid >> 4, tx = tid & 15;

    // load Q tile (already scaled by 1/sqrt(hd) via Wq_eff)
#pragma unroll
    for (int r = 0; r < 2; r++) {
        int idx = tid + r * 256;
        int c = idx >> 4, f = idx & 15;
        ((float4*)&Qs[c][0])[f] = *(const float4*)(Q + (size_t)c * HWN + dtile * 64 + f * 4);
    }

    float m_[4], l_[4], o_[4][2];
#pragma unroll
    for (int i = 0; i < 4; i++) {
        m_[i] = -1e30f; l_[i] = 0.f; o_[i][0] = 0.f; o_[i][1] = 0.f;
    }
    int cc0 = tx, cc1 = tx + 16;

    for (int et = 0; et < 64; et++) {
#pragma unroll
        for (int r = 0; r < 2; r++) {
            int idx = tid + r * 256;
            int c = idx >> 4, f = idx & 15;
            float4 kv = *(const float4*)(K + (size_t)c * HWN + et * 64 + f * 4);
            ((float4*)&Ks[c][0])[f] = kv;
            float4 vv = *(const float4*)(V + (size_t)c * HWN + et * 64 + f * 4);
            *(float4*)&Vs[c][f * 4] = vv;
        }
        __syncthreads();

        // S = Q^T K  (4x4 per thread)
        float s[4][4] = {};
#pragma unroll
        for (int c = 0; c < HD; c++) {
            float4 q4 = *(float4*)&Qs[c][ty * 4];
            float4 k4 = *(float4*)&Ks[c][tx * 4];
            float qa[4] = {q4.x, q4.y, q4.z, q4.w};
            float ka[4] = {k4.x, k4.y, k4.z, k4.w};
#pragma unroll
            for (int i = 0; i < 4; i++)
#pragma unroll
                for (int j = 0; j < 4; j++)
                    s[i][j] += qa[i] * ka[j];
        }

        // online softmax per row; row-group = 16 consecutive lanes (shfl width 16)
#pragma unroll
        for (int i = 0; i < 4; i++) {
            float rmax = fmaxf(fmaxf(s[i][0], s[i][1]), fmaxf(s[i][2], s[i][3]));
#pragma unroll
            for (int off = 8; off > 0; off >>= 1)
                rmax = fmaxf(rmax, __shfl_xor_sync(0xffffffffu, rmax, off, 16));
            float mnew = fmaxf(m_[i], rmax);
            float p0 = __expf(s[i][0] - mnew);
            float p1 = __expf(s[i][1] - mnew);
            float p2 = __expf(s[i][2] - mnew);
            float p3 = __expf(s[i][3] - mnew);
            float rsum = (p0 + p1) + (p2 + p3);
#pragma unroll
            for (int off = 8; off > 0; off >>= 1)
                rsum += __shfl_xor_sync(0xffffffffu, rsum, off, 16);
            float corr = __expf(m_[i] - mnew);
            l_[i] = l_[i] * corr + rsum;
            o_[i][0] *= corr;
            o_[i][1] *= corr;
            m_[i] = mnew;
            float4 pv = {p0, p1, p2, p3};
            *(float4*)&Ps[ty * 4 + i][tx * 4] = pv;
        }
        __syncthreads();

        // O += P V^T : each thread owns rows ty*4..+3, channels {tx, tx+16}
#pragma unroll
        for (int e4 = 0; e4 < 16; e4++) {
            float4 v0 = *(float4*)&Vs[cc0][e4 * 4];
            float4 v1 = *(float4*)&Vs[cc1][e4 * 4];
#pragma unroll
            for (int i = 0; i < 4; i++) {
                float4 p = *(float4*)&Ps[ty * 4 + i][e4 * 4];
                o_[i][0] += p.x * v0.x + p.y * v0.y + p.z * v0.z + p.w * v0.w;
                o_[i][1] += p.x * v1.x + p.y * v1.y + p.z * v1.z + p.w * v1.w;
            }
        }
        __syncthreads();
    }

#pragma unroll
    for (int i = 0; i < 4; i++) {
        float inv = 1.f / l_[i];
        int d = dtile * 64 + ty * 4 + i;
        g_ao[b][n * HD + cc0][d] = o_[i][0] * inv;
        g_ao[b][n * HD + cc1][d] = o_[i][1] * inv;
    }
}

// =================== out projection + residual ===================
__global__ void out_proj_kernel(const float* __restrict__ x, const float* __restrict__ Wout,
                                const float* __restrict__ bout, const float* __restrict__ alpha,
                                float* __restrict__ y) {
    int s0 = blockIdx.x * 64;
    int o0 = blockIdx.y * 64;
    int b = blockIdx.z;
    const float* in = &g_ao[b][0][0];

    __shared__ float Wt[32][68];
    __shared__ float Xt[32][68];
    int tid = threadIdx.x;
    int ty = tid >> 4, tx = tid & 15;
    float acc[4][4] = {};
    for (int cb = 0; cb < 4; cb++) {
#pragma unroll
        for (int r = 0; r < 8; r++) {
            int idx = tid + r * 256;
            int o = idx >> 5, c = idx & 31;
            Wt[c][o] = Wout[(o0 + o) * CCH + cb * 32 + c];
        }
#pragma unroll
        for (int r = 0; r < 2; r++) {
            int idx = tid + r * 256;
            int c = idx >> 4, f = idx & 15;
            float4 v = *(const float4*)(in + (size_t)(cb * 32 + c) * HWN + s0 + f * 4);
            *(float4*)&Xt[c][f * 4] = v;
        }
        __syncthreads();
#pragma unroll
        for (int c = 0; c < 32; c++) {
            float4 wv = *(float4*)&Wt[c][ty * 4];
            float4 xv = *(float4*)&Xt[c][tx * 4];
            float wa[4] = {wv.x, wv.y, wv.z, wv.w};
            float xa[4] = {xv.x, xv.y, xv.z, xv.w};
#pragma unroll
            for (int i = 0; i < 4; i++)
#pragma unroll
                for (int j = 0; j < 4; j++)
                    acc[i][j] += wa[i] * xa[j];
        }
        __syncthreads();
    }
    float a = *alpha;
#pragma unroll
    for (int i = 0; i < 4; i++) {
        int o = o0 + ty * 4 + i;
        float bo = bout[o];
        size_t base = ((size_t)b * CCH + o) * HWN + s0 + tx * 4;
        float4 xv = *(const float4*)(x + base);
        float4 r;
        r.x = xv.x + a * (acc[i][0] + bo);
        r.y = xv.y + a * (acc[i][1] + bo);
        r.z = xv.z + a * (acc[i][2] + bo);
        r.w = xv.w + a * (acc[i][3] + bo);
        *(float4*)(y + base) = r;
    }
}

// =================== launch ===================
extern "C" void kernel_launch(void* const* d_in, const int* in_sizes, int n_in,
                              void* d_out, int out_size) {
    const float* x    = (const float*)d_in[0];
    const float* ctx  = (const float*)d_in[1];
    const float* gq   = (const float*)d_in[2];
    const float* bq   = (const float*)d_in[3];
    const float* gctx = (const float*)d_in[4];
    const float* bctx = (const float*)d_in[5];
    const float* Wq   = (const float*)d_in[6];
    const float* Wk   = (const float*)d_in[7];
    const float* Wv   = (const float*)d_in[8];
    const float* Wout = (const float*)d_in[9];
    const float* bout = (const float*)d_in[10];
    const float* alpha= (const float*)d_in[11];
    float* y = (float*)d_out;

    gn_stats_kernel<<<dim3(32, NB, 2), 256>>>(x, ctx, gq, bq, gctx, bctx);
    eff_weights_kernel<<<dim3(CCH, 3, NB), 128>>>(Wq, Wk, Wv);
    qkv_gemm_kernel<<<dim3(64, 2, NB * 3), 256>>>(x, ctx);
    attn_kernel<<<dim3(64, NB * NHEADS), 256>>>();
    out_proj_kernel<<<dim3(64, 2, NB), 256>>>(x, Wout, bout, alpha, y);
}

// round 3
// speedup vs baseline: 4.6627x; 4.6627x over previous
#include <cuda_runtime.h>
#include <cuda_bf16.h>
#include <cstdint>

#define HWN 4096
#define CCH 128
#define NB 2
#define NHEADS 4
#define HD 32
#define EPSGN 1e-5f
#define SMSCALE 0.17677669529663689f  // 1/sqrt(32)

// -------- scratch (device globals) --------
__device__ float g_scale[2][NB][CCH];
__device__ float g_shift[2][NB][CCH];
__device__ float g_effW[NB][3][CCH][CCH];
__device__ float g_effB[NB][3][CCH];
__device__ __nv_bfloat16 g_qt[NB][HWN][CCH];   // [b][s][ch]  (transposed)
__device__ __nv_bfloat16 g_kt[NB][HWN][CCH];   // [b][s][ch]  (transposed)
__device__ __nv_bfloat16 g_vb[NB][CCH][HWN];   // [b][ch][s]
__device__ float g_ao[NB][CCH][HWN];

#define PACK_BF2(res, lo, hi) \
    asm("cvt.rn.bf16x2.f32 %0, %1, %2;" : "=r"(res) : "f"(hi), "f"(lo))

__device__ __forceinline__ void mma16816(float* d, const uint32_t* a, uint32_t b0, uint32_t b1) {
    asm volatile("mma.sync.aligned.m16n8k16.row.col.f32.bf16.bf16.f32 "
        "{%0,%1,%2,%3}, {%4,%5,%6,%7}, {%8,%9}, {%0,%1,%2,%3};"
        : "+f"(d[0]), "+f"(d[1]), "+f"(d[2]), "+f"(d[3])
        : "r"(a[0]), "r"(a[1]), "r"(a[2]), "r"(a[3]), "r"(b0), "r"(b1));
}

// =================== GroupNorm stats ===================
__global__ void gn_stats_kernel(const float* __restrict__ x, const float* __restrict__ ctx,
                                const float* __restrict__ gq, const float* __restrict__ bq,
                                const float* __restrict__ gc, const float* __restrict__ bc) {
    int g = blockIdx.x, b = blockIdx.y, t = blockIdx.z;
    const float* src = (t == 0 ? x : ctx) + ((size_t)b * CCH + g * 4) * HWN;
    float s = 0.f, s2 = 0.f;
    for (int i = threadIdx.x; i < 4 * HWN; i += 256) {
        float v = src[i]; s += v; s2 += v * v;
    }
    __shared__ float r1[256], r2[256];
    r1[threadIdx.x] = s; r2[threadIdx.x] = s2;
    __syncthreads();
    for (int st = 128; st > 0; st >>= 1) {
        if (threadIdx.x < st) { r1[threadIdx.x] += r1[threadIdx.x + st]; r2[threadIdx.x] += r2[threadIdx.x + st]; }
        __syncthreads();
    }
    __shared__ float mean_s, rstd_s;
    if (threadIdx.x == 0) {
        float mean = r1[0] * (1.f / 16384.f);
        float var  = r2[0] * (1.f / 16384.f) - mean * mean;
        mean_s = mean; rstd_s = rsqrtf(var + EPSGN);
    }
    __syncthreads();
    if (threadIdx.x < 4) {
        int ch = g * 4 + threadIdx.x;
        float gam = (t == 0 ? gq : gc)[ch];
        float bet = (t == 0 ? bq : bc)[ch];
        float sc = rstd_s * gam;
        g_scale[t][b][ch] = sc;
        g_shift[t][b][ch] = bet - mean_s * sc;
    }
}

// =================== effective weights ===================
__global__ void eff_weights_kernel(const float* __restrict__ Wq, const float* __restrict__ Wk,
                                   const float* __restrict__ Wv) {
    int o = blockIdx.x, m = blockIdx.y, b = blockIdx.z;
    int c = threadIdx.x;
    const float* W = (m == 0 ? Wq : m == 1 ? Wk : Wv);
    float w = W[o * CCH + c];
    float sc = 1.f, sh = 0.f;
    if (m == 0)      { sc = g_scale[0][b][c]; sh = g_shift[0][b][c]; }
    else if (m == 1) { sc = g_scale[1][b][c]; sh = g_shift[1][b][c]; }
    float e = w * sc, bb = w * sh;
    if (m == 0) { e *= SMSCALE; bb *= SMSCALE; }
    g_effW[b][m][o][c] = e;
    __shared__ float red[128];
    red[c] = bb;
    __syncthreads();
    for (int st = 64; st > 0; st >>= 1) {
        if (c < st) red[c] += red[c + st];
        __syncthreads();
    }
    if (c == 0) g_effB[b][m][o] = red[0];
}

// =================== QKV GEMM (fp32 FFMA) -> bf16 outputs ===================
__global__ void qkv_gemm_kernel(const float* __restrict__ x, const float* __restrict__ ctx) {
    int s0 = blockIdx.x * 64, o0 = blockIdx.y * 64;
    int bm = blockIdx.z, b = bm / 3, m = bm % 3;
    const float* in = (m == 0 ? x : ctx) + (size_t)b * CCH * HWN;
    const float* W = &g_effW[b][m][0][0];
    __shared__ float Wt[32][68];
    __shared__ float Xt[32][68];
    int tid = threadIdx.x, ty = tid >> 4, tx = tid & 15;
    float acc[4][4] = {};
    for (int cb = 0; cb < 4; cb++) {
#pragma unroll
        for (int r = 0; r < 8; r++) {
            int idx = tid + r * 256, o = idx >> 5, c = idx & 31;
            Wt[c][o] = W[(o0 + o) * CCH + cb * 32 + c];
        }
#pragma unroll
        for (int r = 0; r < 2; r++) {
            int idx = tid + r * 256, c = idx >> 4, f = idx & 15;
            *(float4*)&Xt[c][f * 4] = *(const float4*)(in + (size_t)(cb * 32 + c) * HWN + s0 + f * 4);
        }
        __syncthreads();
#pragma unroll
        for (int c = 0; c < 32; c++) {
            float4 wv = *(float4*)&Wt[c][ty * 4];
            float4 xv = *(float4*)&Xt[c][tx * 4];
            float wa[4] = {wv.x, wv.y, wv.z, wv.w};
            float xa[4] = {xv.x, xv.y, xv.z, xv.w};
#pragma unroll
            for (int i = 0; i < 4; i++)
#pragma unroll
                for (int j = 0; j < 4; j++) acc[i][j] += wa[i] * xa[j];
        }
        __syncthreads();
    }
    if (m == 2) {
        // v: [ch][s] bf16, packed pair stores
#pragma unroll
        for (int i = 0; i < 4; i++) {
            int o = o0 + ty * 4 + i;
            float bias = g_effB[b][2][o];
            uint32_t p0, p1;
            PACK_BF2(p0, acc[i][0] + bias, acc[i][1] + bias);
            PACK_BF2(p1, acc[i][2] + bias, acc[i][3] + bias);
            uint32_t* dst = (uint32_t*)&g_vb[b][o][s0 + tx * 4];
            dst[0] = p0; dst[1] = p1;
        }
    } else {
        __nv_bfloat16* dst = (m == 0 ? &g_qt[b][0][0] : &g_kt[b][0][0]);
#pragma unroll
        for (int i = 0; i < 4; i++) {
            int o = o0 + ty * 4 + i;
            float bias = g_effB[b][m][o];
#pragma unroll
            for (int j = 0; j < 4; j++)
                dst[(size_t)(s0 + tx * 4 + j) * CCH + o] = __float2bfloat16(acc[i][j] + bias);
        }
    }
}

// =================== flash attention on HMMA (mma.sync bf16) ===================
// CTA: 256 thr (8 warps). BM=128 queries (16/warp), BN=128 keys/iter, hd=32.
#define KT_STRIDE 40    // halves per row of Kt/Qt smem tile (80B, 16B-aligned)
#define VS_STRIDE 136   // halves per row of Vs smem tile (272B, 16B-aligned)

__global__ void __launch_bounds__(256) attn_mma_kernel() {
    __shared__ __align__(16) uint16_t Kt[128 * KT_STRIDE];  // [e][ch] (also Q staging)
    __shared__ __align__(16) uint16_t Vs[32 * VS_STRIDE];   // [ch][e]

    int tid = threadIdx.x, warp = tid >> 5, lane = tid & 31;
    int dt = blockIdx.x, bh = blockIdx.y;
    int b = bh >> 2, h = bh & 3;
    int d0 = dt * 128, r0 = warp * 16;
    int l4 = lane >> 2, k0 = (lane & 3) * 2;

    const uint16_t* Qg = (const uint16_t*)&g_qt[b][0][0];
    const uint16_t* Kg = (const uint16_t*)&g_kt[b][0][0];
    const uint16_t* Vg = (const uint16_t*)&g_vb[b][0][0];

    // ---- stage Q tile [128 d][32 ch] into Kt buffer, pull A fragments ----
#pragma unroll
    for (int r = 0; r < 2; r++) {
        int idx = tid + r * 256;
        int e = idx >> 2, q = idx & 3;
        *(uint4*)&Kt[e * KT_STRIDE + q * 8] =
            *(const uint4*)(Qg + (size_t)(d0 + e) * CCH + h * 32 + q * 8);
    }
    __syncthreads();
    uint32_t qf[2][4];
#pragma unroll
    for (int kt = 0; kt < 2; kt++) {
        qf[kt][0] = *(uint32_t*)&Kt[(r0 + l4) * KT_STRIDE + kt * 16 + k0];
        qf[kt][1] = *(uint32_t*)&Kt[(r0 + l4 + 8) * KT_STRIDE + kt * 16 + k0];
        qf[kt][2] = *(uint32_t*)&Kt[(r0 + l4) * KT_STRIDE + kt * 16 + k0 + 8];
        qf[kt][3] = *(uint32_t*)&Kt[(r0 + l4 + 8) * KT_STRIDE + kt * 16 + k0 + 8];
    }

    float O[4][4] = {};
    float ls0 = 0.f, ls1 = 0.f;

    for (int et = 0; et < 32; et++) {
        int e0 = et * 128;
        __syncthreads();   // previous iter's smem consumers done
        // K tile [128 e][32 ch]
#pragma unroll
        for (int r = 0; r < 2; r++) {
            int idx = tid + r * 256;
            int e = idx >> 2, q = idx & 3;
            *(uint4*)&Kt[e * KT_STRIDE + q * 8] =
                *(const uint4*)(Kg + (size_t)(e0 + e) * CCH + h * 32 + q * 8);
        }
        // V tile [32 ch][128 e]
#pragma unroll
        for (int r = 0; r < 2; r++) {
            int idx = tid + r * 256;
            int c = idx >> 4, q = idx & 15;
            *(uint4*)&Vs[c * VS_STRIDE + q * 8] =
                *(const uint4*)(Vg + (size_t)(h * 32 + c) * HWN + e0 + q * 8);
        }
        __syncthreads();

        // ---- MMA1: S[16 x 128] per warp ----
        float S[16][4];
#pragma unroll
        for (int nt = 0; nt < 16; nt++) { S[nt][0] = S[nt][1] = S[nt][2] = S[nt][3] = 0.f; }
#pragma unroll
        for (int kt = 0; kt < 2; kt++) {
#pragma unroll
            for (int nt = 0; nt < 16; nt++) {
                uint32_t b0 = *(uint32_t*)&Kt[(nt * 8 + l4) * KT_STRIDE + kt * 16 + k0];
                uint32_t b1 = *(uint32_t*)&Kt[(nt * 8 + l4) * KT_STRIDE + kt * 16 + k0 + 8];
                mma16816(S[nt], qf[kt], b0, b1);
            }
        }

        // ---- softmax (no max pass): P = exp(S), track row sums, pack to A frags ----
        uint32_t pf[8][4];
#pragma unroll
        for (int t = 0; t < 8; t++) {
            float e00 = __expf(S[2 * t][0]),     e01 = __expf(S[2 * t][1]);
            float e02 = __expf(S[2 * t][2]),     e03 = __expf(S[2 * t][3]);
            float e10 = __expf(S[2 * t + 1][0]), e11 = __expf(S[2 * t + 1][1]);
            float e12 = __expf(S[2 * t + 1][2]), e13 = __expf(S[2 * t + 1][3]);
            ls0 += (e00 + e01) + (e10 + e11);
            ls1 += (e02 + e03) + (e12 + e13);
            PACK_BF2(pf[t][0], e00, e01);
            PACK_BF2(pf[t][1], e02, e03);
            PACK_BF2(pf[t][2], e10, e11);
            PACK_BF2(pf[t][3], e12, e13);
        }

        // ---- MMA2: O[16 x 32] += P V^T ----
#pragma unroll
        for (int kt = 0; kt < 8; kt++) {
#pragma unroll
            for (int nt = 0; nt < 4; nt++) {
                uint32_t b0 = *(uint32_t*)&Vs[(nt * 8 + l4) * VS_STRIDE + kt * 16 + k0];
                uint32_t b1 = *(uint32_t*)&Vs[(nt * 8 + l4) * VS_STRIDE + kt * 16 + k0 + 8];
                mma16816(O[nt], pf[kt], b0, b1);
            }
        }
    }

    // ---- epilogue: reduce row sums over the 4 lanes of each row, normalize, store ----
    ls0 += __shfl_xor_sync(0xffffffffu, ls0, 1);
    ls0 += __shfl_xor_sync(0xffffffffu, ls0, 2);
    ls1 += __shfl_xor_sync(0xffffffffu, ls1, 1);
    ls1 += __shfl_xor_sync(0xffffffffu, ls1, 2);
    float inv0 = 1.f / ls0, inv1 = 1.f / ls1;
    int d = d0 + r0 + l4;
#pragma unroll
    for (int nt = 0; nt < 4; nt++) {
        int ch = h * 32 + nt * 8 + (lane & 3) * 2;
        g_ao[b][ch][d]         = O[nt][0] * inv0;
        g_ao[b][ch + 1][d]     = O[nt][1] * inv0;
        g_ao[b][ch][d + 8]     = O[nt][2] * inv1;
        g_ao[b][ch + 1][d + 8] = O[nt][3] * inv1;
    }
}

// =================== out projection + residual ===================
__global__ void out_proj_kernel(const float* __restrict__ x, const float* __restrict__ Wout,
                                const float* __restrict__ bout, const float* __restrict__ alpha,
                                float* __restrict__ y) {
    int s0 = blockIdx.x * 64, o0 = blockIdx.y * 64, b = blockIdx.z;
    const float* in = &g_ao[b][0][0];
    __shared__ float Wt[32][68];
    __shared__ float Xt[32][68];
    int tid = threadIdx.x, ty = tid >> 4, tx = tid & 15;
    float acc[4][4] = {};
    for (int cb = 0; cb < 4; cb++) {
#pragma unroll
        for (int r = 0; r < 8; r++) {
            int idx = tid + r * 256, o = idx >> 5, c = idx & 31;
            Wt[c][o] = Wout[(o0 + o) * CCH + cb * 32 + c];
        }
#pragma unroll
        for (int r = 0; r < 2; r++) {
            int idx = tid + r * 256, c = idx >> 4, f = idx & 15;
            *(float4*)&Xt[c][f * 4] = *(const float4*)(in + (size_t)(cb * 32 + c) * HWN + s0 + f * 4);
        }
        __syncthreads();
#pragma unroll
        for (int c = 0; c < 32; c++) {
            float4 wv = *(float4*)&Wt[c][ty * 4];
            float4 xv = *(float4*)&Xt[c][tx * 4];
            float wa[4] = {wv.x, wv.y, wv.z, wv.w};
            float xa[4] = {xv.x, xv.y, xv.z, xv.w};
#pragma unroll
            for (int i = 0; i < 4; i++)
#pragma unroll
                for (int j = 0; j < 4; j++) acc[i][j] += wa[i] * xa[j];
        }
        __syncthreads();
    }
    float a = *alpha;
#pragma unroll
    for (int i = 0; i < 4; i++) {
        int o = o0 + ty * 4 + i;
        float bo = bout[o];
        size_t base = ((size_t)b * CCH + o) * HWN + s0 + tx * 4;
        float4 xv = *(const float4*)(x + base);
        float4 r;
        r.x = xv.x + a * (acc[i][0] + bo);
        r.y = xv.y + a * (acc[i][1] + bo);
        r.z = xv.z + a * (acc[i][2] + bo);
        r.w = xv.w + a * (acc[i][3] + bo);
        *(float4*)(y + base) = r;
    }
}

// =================== launch ===================
extern "C" void kernel_launch(void* const* d_in, const int* in_sizes, int n_in,
                              void* d_out, int out_size) {
    const float* x    = (const float*)d_in[0];
    const float* ctx  = (const float*)d_in[1];
    const float* gq   = (const float*)d_in[2];
    const float* bq   = (const float*)d_in[3];
    const float* gctx = (const float*)d_in[4];
    const float* bctx = (const float*)d_in[5];
    const float* Wq   = (const float*)d_in[6];
    const float* Wk   = (const float*)d_in[7];
    const float* Wv   = (const float*)d_in[8];
    const float* Wout = (const float*)d_in[9];
    const float* bout = (const float*)d_in[10];
    const float* alpha= (const float*)d_in[11];
    float* y = (float*)d_out;

    gn_stats_kernel<<<dim3(32, NB, 2), 256>>>(x, ctx, gq, bq, gctx, bctx);
    eff_weights_kernel<<<dim3(CCH, 3, NB), 128>>>(Wq, Wk, Wv);
    qkv_gemm_kernel<<<dim3(64, 2, NB * 3), 256>>>(x, ctx);
    attn_mma_kernel<<<dim3(32, NB * NHEADS), 256>>>();
    out_proj_kernel<<<dim3(64, 2, NB), 256>>>(x, Wout, bout, alpha, y);
}

// round 4
// speedup vs baseline: 6.2098x; 1.3318x over previous
#include <cuda_runtime.h>
#include <cuda_bf16.h>
#include <cstdint>

#define HWN 4096
#define CCH 128
#define NB 2
#define NHEADS 4
#define HD 32
#define EPSGN 1e-5f
#define SMSCALE 0.17677669529663689f  // 1/sqrt(32)

// -------- scratch (device globals) --------
__device__ float g_scale[2][NB][CCH];
__device__ float g_shift[2][NB][CCH];
__device__ float g_effB[NB][3][CCH];
__device__ __nv_bfloat16 g_effWh[NB][3][CCH][CCH];
__device__ __nv_bfloat16 g_q[NB][CCH][HWN];   // [b][ch][s] bf16
__device__ __nv_bfloat16 g_k[NB][CCH][HWN];
__device__ __nv_bfloat16 g_v[NB][CCH][HWN];
__device__ float g_ao[NB][CCH][HWN];

#define PACK_BF2(res, lo, hi) \
    asm("cvt.rn.bf16x2.f32 %0, %1, %2;" : "=r"(res) : "f"(hi), "f"(lo))

__device__ __forceinline__ uint32_t smem_u32(const void* p) {
    uint32_t a;
    asm("{ .reg .u64 t; cvta.to.shared.u64 t, %1; cvt.u32.u64 %0, t; }" : "=r"(a) : "l"(p));
    return a;
}
__device__ __forceinline__ void mma16816(float* d, const uint32_t* a, uint32_t b0, uint32_t b1) {
    asm volatile("mma.sync.aligned.m16n8k16.row.col.f32.bf16.bf16.f32 "
        "{%0,%1,%2,%3}, {%4,%5,%6,%7}, {%8,%9}, {%0,%1,%2,%3};"
        : "+f"(d[0]), "+f"(d[1]), "+f"(d[2]), "+f"(d[3])
        : "r"(a[0]), "r"(a[1]), "r"(a[2]), "r"(a[3]), "r"(b0), "r"(b1));
}
#define LDSM_X4(r, a) \
    asm volatile("ldmatrix.sync.aligned.m8n8.x4.shared.b16 {%0,%1,%2,%3}, [%4];" \
        : "=r"((r)[0]), "=r"((r)[1]), "=r"((r)[2]), "=r"((r)[3]) : "r"(a))
#define LDSM_X4T(r, a) \
    asm volatile("ldmatrix.sync.aligned.m8n8.x4.trans.shared.b16 {%0,%1,%2,%3}, [%4];" \
        : "=r"((r)[0]), "=r"((r)[1]), "=r"((r)[2]), "=r"((r)[3]) : "r"(a))
__device__ __forceinline__ void cp16(uint32_t dst, const void* src) {
    asm volatile("cp.async.cg.shared.global [%0], [%1], 16;" :: "r"(dst), "l"(src));
}
#define CP_COMMIT() asm volatile("cp.async.commit_group;" ::: "memory")
#define CP_WAIT0()  asm volatile("cp.async.wait_group 0;" ::: "memory")

// =================== GroupNorm stats ===================
__global__ void gn_stats_kernel(const float* __restrict__ x, const float* __restrict__ ctx,
                                const float* __restrict__ gq, const float* __restrict__ bq,
                                const float* __restrict__ gc, const float* __restrict__ bc) {
    int g = blockIdx.x, b = blockIdx.y, t = blockIdx.z;
    const float* src = (t == 0 ? x : ctx) + ((size_t)b * CCH + g * 4) * HWN;
    float s = 0.f, s2 = 0.f;
    for (int i = threadIdx.x; i < 4 * HWN; i += 256) {
        float v = src[i]; s += v; s2 += v * v;
    }
    __shared__ float r1[256], r2[256];
    r1[threadIdx.x] = s; r2[threadIdx.x] = s2;
    __syncthreads();
    for (int st = 128; st > 0; st >>= 1) {
        if (threadIdx.x < st) { r1[threadIdx.x] += r1[threadIdx.x + st]; r2[threadIdx.x] += r2[threadIdx.x + st]; }
        __syncthreads();
    }
    __shared__ float mean_s, rstd_s;
    if (threadIdx.x == 0) {
        float mean = r1[0] * (1.f / 16384.f);
        float var  = r2[0] * (1.f / 16384.f) - mean * mean;
        mean_s = mean; rstd_s = rsqrtf(var + EPSGN);
    }
    __syncthreads();
    if (threadIdx.x < 4) {
        int ch = g * 4 + threadIdx.x;
        float gam = (t == 0 ? gq : gc)[ch];
        float bet = (t == 0 ? bq : bc)[ch];
        float sc = rstd_s * gam;
        g_scale[t][b][ch] = sc;
        g_shift[t][b][ch] = bet - mean_s * sc;
    }
}

// =================== effective weights (fp32 math -> bf16 weights) ===================
__global__ void eff_weights_kernel(const float* __restrict__ Wq, const float* __restrict__ Wk,
                                   const float* __restrict__ Wv) {
    int o = blockIdx.x, m = blockIdx.y, b = blockIdx.z;
    int c = threadIdx.x;
    const float* W = (m == 0 ? Wq : m == 1 ? Wk : Wv);
    float w = W[o * CCH + c];
    float sc = 1.f, sh = 0.f;
    if (m == 0)      { sc = g_scale[0][b][c]; sh = g_shift[0][b][c]; }
    else if (m == 1) { sc = g_scale[1][b][c]; sh = g_shift[1][b][c]; }
    float e = w * sc, bb = w * sh;
    if (m == 0) { e *= SMSCALE; bb *= SMSCALE; }
    g_effWh[b][m][o][c] = __float2bfloat16(e);
    __shared__ float red[128];
    red[c] = bb;
    __syncthreads();
    for (int st = 64; st > 0; st >>= 1) {
        if (c < st) red[c] += red[c + st];
        __syncthreads();
    }
    if (c == 0) g_effB[b][m][o] = red[0];
}

// =================== QKV GEMM on HMMA ===================
// out[o=128][s-tile=128] = Weff[o][c=128] x in[c][s].  grid (32 stiles, 6 bm), 256 thr.
#define WST 136   // halves stride of W tile
#define XST 136   // halves stride of act chunk

__global__ void __launch_bounds__(256) qkv_mma_kernel(const float* __restrict__ x,
                                                      const float* __restrict__ ctx) {
    __shared__ __align__(16) uint16_t Ws[128 * WST];
    __shared__ __align__(16) uint16_t Xs[32 * XST];

    int tid = threadIdx.x, warp = tid >> 5, lane = tid & 31;
    int l4 = lane >> 2, k2 = (lane & 3) * 2;
    int mid = lane >> 3, rr = lane & 7;
    int s0 = blockIdx.x * 128;
    int bm = blockIdx.y, b = bm / 3, m = bm % 3;
    const float* in = (m == 0 ? x : ctx) + (size_t)b * CCH * HWN;
    __nv_bfloat16* out = (m == 0 ? &g_q[b][0][0] : m == 1 ? &g_k[b][0][0] : &g_v[b][0][0]);

    // stage W tile bf16 [128o][128c]
    {
        int o = tid >> 1, part = (tid & 1) * 64;
        const uint16_t* src = (const uint16_t*)&g_effWh[b][m][o][part];
#pragma unroll
        for (int i = 0; i < 8; i++)
            *(uint4*)&Ws[o * WST + part + i * 8] = *(const uint4*)(src + i * 8);
    }
    __syncthreads();

    // A-frags: warp's 16 o-rows, all 8 k-steps (c dim)
    int o0 = warp * 16;
    uint32_t af[8][4];
#pragma unroll
    for (int kt = 0; kt < 8; kt++) {
        af[kt][0] = *(uint32_t*)&Ws[(o0 + l4) * WST + kt * 16 + k2];
        af[kt][1] = *(uint32_t*)&Ws[(o0 + l4 + 8) * WST + kt * 16 + k2];
        af[kt][2] = *(uint32_t*)&Ws[(o0 + l4) * WST + kt * 16 + k2 + 8];
        af[kt][3] = *(uint32_t*)&Ws[(o0 + l4 + 8) * WST + kt * 16 + k2 + 8];
    }

    float acc[16][4] = {};
    uint32_t xbase = smem_u32(Xs);

    for (int c4 = 0; c4 < 4; c4++) {
        // load act chunk [32c][128s] fp32 -> bf16 regs
        int c = tid >> 3, seg = (tid & 7) * 16;
        const float* src = in + (size_t)(c4 * 32 + c) * HWN + s0 + seg;
        float4 f0 = *(const float4*)(src);
        float4 f1 = *(const float4*)(src + 4);
        float4 f2 = *(const float4*)(src + 8);
        float4 f3 = *(const float4*)(src + 12);
        uint32_t p[8];
        PACK_BF2(p[0], f0.x, f0.y); PACK_BF2(p[1], f0.z, f0.w);
        PACK_BF2(p[2], f1.x, f1.y); PACK_BF2(p[3], f1.z, f1.w);
        PACK_BF2(p[4], f2.x, f2.y); PACK_BF2(p[5], f2.z, f2.w);
        PACK_BF2(p[6], f3.x, f3.y); PACK_BF2(p[7], f3.z, f3.w);
        __syncthreads();   // previous chunk consumers done
        *(uint4*)&Xs[c * XST + seg]     = make_uint4(p[0], p[1], p[2], p[3]);
        *(uint4*)&Xs[c * XST + seg + 8] = make_uint4(p[4], p[5], p[6], p[7]);
        __syncthreads();

#pragma unroll
        for (int kt = 0; kt < 2; kt++) {
#pragma unroll
            for (int pp = 0; pp < 8; pp++) {
                int c_row = kt * 16 + (mid & 1) * 8 + rr;
                int s_col = pp * 16 + (mid >> 1) * 8;
                uint32_t bf[4];
                LDSM_X4T(bf, xbase + (uint32_t)(c_row * XST + s_col) * 2u);
                mma16816(acc[2 * pp],     af[c4 * 2 + kt], bf[0], bf[1]);
                mma16816(acc[2 * pp + 1], af[c4 * 2 + kt], bf[2], bf[3]);
            }
        }
    }

    // epilogue: bias + pack to bf16 [ch][s]
    float b0 = g_effB[b][m][o0 + l4];
    float b1 = g_effB[b][m][o0 + l4 + 8];
#pragma unroll
    for (int nt = 0; nt < 16; nt++) {
        int s = s0 + nt * 8 + k2;
        uint32_t lo, hi;
        PACK_BF2(lo, acc[nt][0] + b0, acc[nt][1] + b0);
        PACK_BF2(hi, acc[nt][2] + b1, acc[nt][3] + b1);
        *(uint32_t*)&out[(size_t)(o0 + l4) * HWN + s]     = lo;
        *(uint32_t*)&out[(size_t)(o0 + l4 + 8) * HWN + s] = hi;
    }
}

// =================== flash attention: HMMA + cp.async pipeline + ldmatrix ===================
#define AST 136                    // halves stride (272B rows)
#define TBUF (32 * AST * 2)        // bytes per tile buffer

__global__ void __launch_bounds__(256) attn_mma_kernel() {
    __shared__ __align__(16) uint16_t Qs[32 * AST];
    __shared__ __align__(16) uint16_t Ks[2][32 * AST];
    __shared__ __align__(16) uint16_t Vs[2][32 * AST];

    int tid = threadIdx.x, warp = tid >> 5, lane = tid & 31;
    int l4 = lane >> 2, mid = lane >> 3, rr = lane & 7;
    int dt = blockIdx.x, bh = blockIdx.y;
    int b = bh >> 2, h = bh & 3;
    int d0 = dt * 128, r0 = warp * 16;

    const uint16_t* Qg = (const uint16_t*)&g_q[b][h * HD][0];
    const uint16_t* Kg = (const uint16_t*)&g_k[b][h * HD][0];
    const uint16_t* Vg = (const uint16_t*)&g_v[b][h * HD][0];

    uint32_t kbase = smem_u32(Ks);
    uint32_t vbase = smem_u32(Vs);

    int sc = tid >> 3, sseg = (tid & 7) * 16;

    // ---- stage Q tile [32ch][128d], extract A-frags via ldmatrix.trans ----
    {
        const uint16_t* src = Qg + (size_t)sc * HWN + d0 + sseg;
        *(uint4*)&Qs[sc * AST + sseg]     = *(const uint4*)(src);
        *(uint4*)&Qs[sc * AST + sseg + 8] = *(const uint4*)(src + 8);
    }
    __syncthreads();
    uint32_t qf[2][4];
    {
        uint32_t qb = smem_u32(Qs);
#pragma unroll
        for (int kt = 0; kt < 2; kt++) {
            int c_row = kt * 16 + (mid >> 1) * 8 + rr;
            int m_col = r0 + (mid & 1) * 8;
            LDSM_X4T(qf[kt], qb + (uint32_t)(c_row * AST + m_col) * 2u);
        }
    }
    __syncthreads();

    // ---- prologue: async-load tile 0 ----
    {
        uint32_t kd = kbase + (uint32_t)(sc * AST + sseg) * 2u;
        uint32_t vd = vbase + (uint32_t)(sc * AST + sseg) * 2u;
        cp16(kd,      Kg + (size_t)sc * HWN + sseg);
        cp16(kd + 16, Kg + (size_t)sc * HWN + sseg + 8);
        cp16(vd,      Vg + (size_t)sc * HWN + sseg);
        cp16(vd + 16, Vg + (size_t)sc * HWN + sseg + 8);
    }
    CP_COMMIT();

    float O[4][4] = {};
    float ls0 = 0.f, ls1 = 0.f;

    for (int et = 0; et < 32; et++) {
        int buf = et & 1;
        CP_WAIT0();
        __syncthreads();
        if (et + 1 < 32) {
            int e1 = (et + 1) * 128;
            uint32_t kd = kbase + (uint32_t)(buf ^ 1) * TBUF + (uint32_t)(sc * AST + sseg) * 2u;
            uint32_t vd = vbase + (uint32_t)(buf ^ 1) * TBUF + (uint32_t)(sc * AST + sseg) * 2u;
            cp16(kd,      Kg + (size_t)sc * HWN + e1 + sseg);
            cp16(kd + 16, Kg + (size_t)sc * HWN + e1 + sseg + 8);
            cp16(vd,      Vg + (size_t)sc * HWN + e1 + sseg);
            cp16(vd + 16, Vg + (size_t)sc * HWN + e1 + sseg + 8);
        }
        CP_COMMIT();

        // ---- MMA1: S[16 x 128] ----
        float S[16][4];
#pragma unroll
        for (int nt = 0; nt < 16; nt++) { S[nt][0] = S[nt][1] = S[nt][2] = S[nt][3] = 0.f; }
#pragma unroll
        for (int kt = 0; kt < 2; kt++) {
#pragma unroll
            for (int pp = 0; pp < 8; pp++) {
                int c_row = kt * 16 + (mid & 1) * 8 + rr;
                int n_col = pp * 16 + (mid >> 1) * 8;
                uint32_t bf[4];
                LDSM_X4T(bf, kbase + (uint32_t)buf * TBUF + (uint32_t)(c_row * AST + n_col) * 2u);
                mma16816(S[2 * pp],     qf[kt], bf[0], bf[1]);
                mma16816(S[2 * pp + 1], qf[kt], bf[2], bf[3]);
            }
        }

        // ---- softmax (no max pass) ----
        uint32_t pf[8][4];
#pragma unroll
        for (int t = 0; t < 8; t++) {
            float e00 = __expf(S[2 * t][0]),     e01 = __expf(S[2 * t][1]);
            float e02 = __expf(S[2 * t][2]),     e03 = __expf(S[2 * t][3]);
            float e10 = __expf(S[2 * t + 1][0]), e11 = __expf(S[2 * t + 1][1]);
            float e12 = __expf(S[2 * t + 1][2]), e13 = __expf(S[2 * t + 1][3]);
            ls0 += (e00 + e01) + (e10 + e11);
            ls1 += (e02 + e03) + (e12 + e13);
            PACK_BF2(pf[t][0], e00, e01);
            PACK_BF2(pf[t][1], e02, e03);
            PACK_BF2(pf[t][2], e10, e11);
            PACK_BF2(pf[t][3], e12, e13);
        }

        // ---- MMA2: O[16 x 32] += P V^T ----
#pragma unroll
        for (int kt = 0; kt < 8; kt++) {
#pragma unroll
            for (int pp = 0; pp < 2; pp++) {
                int n_row = pp * 16 + (mid >> 1) * 8 + rr;
                int koff  = kt * 16 + (mid & 1) * 8;
                uint32_t bf[4];
                LDSM_X4(bf, vbase + (uint32_t)buf * TBUF + (uint32_t)(n_row * AST + koff) * 2u);
                mma16816(O[2 * pp],     pf[kt], bf[0], bf[1]);
                mma16816(O[2 * pp + 1], pf[kt], bf[2], bf[3]);
            }
        }
    }

    // ---- epilogue ----
    ls0 += __shfl_xor_sync(0xffffffffu, ls0, 1);
    ls0 += __shfl_xor_sync(0xffffffffu, ls0, 2);
    ls1 += __shfl_xor_sync(0xffffffffu, ls1, 1);
    ls1 += __shfl_xor_sync(0xffffffffu, ls1, 2);
    float inv0 = 1.f / ls0, inv1 = 1.f / ls1;
    int d = d0 + r0 + l4;
#pragma unroll
    for (int nt = 0; nt < 4; nt++) {
        int ch = h * HD + nt * 8 + (lane & 3) * 2;
        g_ao[b][ch][d]         = O[nt][0] * inv0;
        g_ao[b][ch + 1][d]     = O[nt][1] * inv0;
        g_ao[b][ch][d + 8]     = O[nt][2] * inv1;
        g_ao[b][ch + 1][d + 8] = O[nt][3] * inv1;
    }
}

// =================== out projection + residual ===================
__global__ void out_proj_kernel(const float* __restrict__ x, const float* __restrict__ Wout,
                                const float* __restrict__ bout, const float* __restrict__ alpha,
                                float* __restrict__ y) {
    int s0 = blockIdx.x * 64, o0 = blockIdx.y * 64, b = blockIdx.z;
    const float* in = &g_ao[b][0][0];
    __shared__ float Wt[32][68];
    __shared__ float Xt[32][68];
    int tid = threadIdx.x, ty = tid >> 4, tx = tid & 15;
    float acc[4][4] = {};
    for (int cb = 0; cb < 4; cb++) {
#pragma unroll
        for (int r = 0; r < 8; r++) {
            int idx = tid + r * 256, o = idx >> 5, c = idx & 31;
            Wt[c][o] = Wout[(o0 + o) * CCH + cb * 32 + c];
        }
#pragma unroll
        for (int r = 0; r < 2; r++) {
            int idx = tid + r * 256, c = idx >> 4, f = idx & 15;
            *(float4*)&Xt[c][f * 4] = *(const float4*)(in + (size_t)(cb * 32 + c) * HWN + s0 + f * 4);
        }
        __syncthreads();
#pragma unroll
        for (int c = 0; c < 32; c++) {
            float4 wv = *(float4*)&Wt[c][ty * 4];
            float4 xv = *(float4*)&Xt[c][tx * 4];
            float wa[4] = {wv.x, wv.y, wv.z, wv.w};
            float xa[4] = {xv.x, xv.y, xv.z, xv.w};
#pragma unroll
            for (int i = 0; i < 4; i++)
#pragma unroll
                for (int j = 0; j < 4; j++) acc[i][j] += wa[i] * xa[j];
        }
        __syncthreads();
    }
    float a = *alpha;
#pragma unroll
    for (int i = 0; i < 4; i++) {
        int o = o0 + ty * 4 + i;
        float bo = bout[o];
        size_t base = ((size_t)b * CCH + o) * HWN + s0 + tx * 4;
        float4 xv = *(const float4*)(x + base);
        float4 r;
        r.x = xv.x + a * (acc[i][0] + bo);
        r.y = xv.y + a * (acc[i][1] + bo);
        r.z = xv.z + a * (acc[i][2] + bo);
        r.w = xv.w + a * (acc[i][3] + bo);
        *(float4*)(y + base) = r;
    }
}

// =================== launch ===================
extern "C" void kernel_launch(void* const* d_in, const int* in_sizes, int n_in,
                              void* d_out, int out_size) {
    const float* x    = (const float*)d_in[0];
    const float* ctx  = (const float*)d_in[1];
    const float* gq   = (const float*)d_in[2];
    const float* bq   = (const float*)d_in[3];
    const float* gctx = (const float*)d_in[4];
    const float* bctx = (const float*)d_in[5];
    const float* Wq   = (const float*)d_in[6];
    const float* Wk   = (const float*)d_in[7];
    const float* Wv   = (const float*)d_in[8];
    const float* Wout = (const float*)d_in[9];
    const float* bout = (const float*)d_in[10];
    const float* alpha= (const float*)d_in[11];
    float* y = (float*)d_out;

    gn_stats_kernel<<<dim3(32, NB, 2), 256>>>(x, ctx, gq, bq, gctx, bctx);
    eff_weights_kernel<<<dim3(CCH, 3, NB), 128>>>(Wq, Wk, Wv);
    qkv_mma_kernel<<<dim3(32, NB * 3), 256>>>(x, ctx);
    attn_mma_kernel<<<dim3(32, NB * NHEADS), 256>>>();
    out_proj_kernel<<<dim3(64, 2, NB), 256>>>(x, Wout, bout, alpha, y);
}

// round 5
// speedup vs baseline: 6.3334x; 1.0199x over previous
#include <cuda_runtime.h>
#include <cuda_bf16.h>
#include <cstdint>

#define HWN 4096
#define CCH 128
#define NB 2
#define NHEADS 4
#define HD 32
#define EPSGN 1e-5f
// (1/sqrt(32)) * log2(e)  -- folds softmax scale AND exp->ex2 conversion into Wq
#define SMSCALE 0.25504733054577454f

// -------- scratch (device globals) --------
__device__ float g_scale[2][NB][CCH];
__device__ float g_shift[2][NB][CCH];
__device__ float g_effB[NB][3][CCH];
__device__ __nv_bfloat16 g_effWh[NB][3][CCH][CCH];
__device__ __nv_bfloat16 g_Wouth[CCH][CCH];
__device__ __nv_bfloat16 g_q[NB][CCH][HWN];   // [b][ch][s] bf16
__device__ __nv_bfloat16 g_k[NB][CCH][HWN];
__device__ __nv_bfloat16 g_v[NB][CCH][HWN];
__device__ float g_po[2][NB * NHEADS][32][128][32];  // [split][bh][dt][row][ch] unnormalized O
__device__ float g_pl[2][NB * NHEADS][HWN];          // [split][bh][d] row sums
__device__ __nv_bfloat16 g_ao[NB][CCH][HWN];         // attention out, bf16 [ch][s]

#define PACK_BF2(res, lo, hi) \
    asm("cvt.rn.bf16x2.f32 %0, %1, %2;" : "=r"(res) : "f"(hi), "f"(lo))
#define EX2(res, xin) \
    asm("ex2.approx.f32 %0, %1;" : "=f"(res) : "f"(xin))

__device__ __forceinline__ uint32_t smem_u32(const void* p) {
    uint32_t a;
    asm("{ .reg .u64 t; cvta.to.shared.u64 t, %1; cvt.u32.u64 %0, t; }" : "=r"(a) : "l"(p));
    return a;
}
__device__ __forceinline__ void mma16816(float* d, const uint32_t* a, uint32_t b0, uint32_t b1) {
    asm volatile("mma.sync.aligned.m16n8k16.row.col.f32.bf16.bf16.f32 "
        "{%0,%1,%2,%3}, {%4,%5,%6,%7}, {%8,%9}, {%0,%1,%2,%3};"
        : "+f"(d[0]), "+f"(d[1]), "+f"(d[2]), "+f"(d[3])
        : "r"(a[0]), "r"(a[1]), "r"(a[2]), "r"(a[3]), "r"(b0), "r"(b1));
}
#define LDSM_X4(r, a) \
    asm volatile("ldmatrix.sync.aligned.m8n8.x4.shared.b16 {%0,%1,%2,%3}, [%4];" \
        : "=r"((r)[0]), "=r"((r)[1]), "=r"((r)[2]), "=r"((r)[3]) : "r"(a))
#define LDSM_X4T(r, a) \
    asm volatile("ldmatrix.sync.aligned.m8n8.x4.trans.shared.b16 {%0,%1,%2,%3}, [%4];" \
        : "=r"((r)[0]), "=r"((r)[1]), "=r"((r)[2]), "=r"((r)[3]) : "r"(a))
__device__ __forceinline__ void cp16(uint32_t dst, const void* src) {
    asm volatile("cp.async.cg.shared.global [%0], [%1], 16;" :: "r"(dst), "l"(src));
}
#define CP_COMMIT() asm volatile("cp.async.commit_group;" ::: "memory")
#define CP_WAIT0()  asm volatile("cp.async.wait_group 0;" ::: "memory")

// =================== GroupNorm stats ===================
__global__ void gn_stats_kernel(const float* __restrict__ x, const float* __restrict__ ctx,
                                const float* __restrict__ gq, const float* __restrict__ bq,
                                const float* __restrict__ gc, const float* __restrict__ bc) {
    int g = blockIdx.x, b = blockIdx.y, t = blockIdx.z;
    const float* src = (t == 0 ? x : ctx) + ((size_t)b * CCH + g * 4) * HWN;
    float s = 0.f, s2 = 0.f;
    for (int i = threadIdx.x; i < 4 * HWN; i += 256) {
        float v = src[i]; s += v; s2 += v * v;
    }
    __shared__ float r1[256], r2[256];
    r1[threadIdx.x] = s; r2[threadIdx.x] = s2;
    __syncthreads();
    for (int st = 128; st > 0; st >>= 1) {
        if (threadIdx.x < st) { r1[threadIdx.x] += r1[threadIdx.x + st]; r2[threadIdx.x] += r2[threadIdx.x + st]; }
        __syncthreads();
    }
    __shared__ float mean_s, rstd_s;
    if (threadIdx.x == 0) {
        float mean = r1[0] * (1.f / 16384.f);
        float var  = r2[0] * (1.f / 16384.f) - mean * mean;
        mean_s = mean; rstd_s = rsqrtf(var + EPSGN);
    }
    __syncthreads();
    if (threadIdx.x < 4) {
        int ch = g * 4 + threadIdx.x;
        float gam = (t == 0 ? gq : gc)[ch];
        float bet = (t == 0 ? bq : bc)[ch];
        float sc = rstd_s * gam;
        g_scale[t][b][ch] = sc;
        g_shift[t][b][ch] = bet - mean_s * sc;
    }
}

// =================== effective weights + Wout bf16 ===================
__global__ void eff_weights_kernel(const float* __restrict__ Wq, const float* __restrict__ Wk,
                                   const float* __restrict__ Wv, const float* __restrict__ Wout) {
    int o = blockIdx.x, m = blockIdx.y, b = blockIdx.z;
    int c = threadIdx.x;
    if (m == 3) {
        if (b == 0) g_Wouth[o][c] = __float2bfloat16(Wout[o * CCH + c]);
        return;
    }
    const float* W = (m == 0 ? Wq : m == 1 ? Wk : Wv);
    float w = W[o * CCH + c];
    float sc = 1.f, sh = 0.f;
    if (m == 0)      { sc = g_scale[0][b][c]; sh = g_shift[0][b][c]; }
    else if (m == 1) { sc = g_scale[1][b][c]; sh = g_shift[1][b][c]; }
    float e = w * sc, bb = w * sh;
    if (m == 0) { e *= SMSCALE; bb *= SMSCALE; }
    g_effWh[b][m][o][c] = __float2bfloat16(e);
    __shared__ float red[128];
    red[c] = bb;
    __syncthreads();
    for (int st = 64; st > 0; st >>= 1) {
        if (c < st) red[c] += red[c + st];
        __syncthreads();
    }
    if (c == 0) g_effB[b][m][o] = red[0];
}

// =================== QKV GEMM on HMMA ===================
#define WST 136
#define XST 136

__global__ void __launch_bounds__(256) qkv_mma_kernel(const float* __restrict__ x,
                                                      const float* __restrict__ ctx) {
    __shared__ __align__(16) uint16_t Ws[128 * WST];
    __shared__ __align__(16) uint16_t Xs[32 * XST];

    int tid = threadIdx.x, warp = tid >> 5, lane = tid & 31;
    int l4 = lane >> 2, k2 = (lane & 3) * 2;
    int mid = lane >> 3, rr = lane & 7;
    int s0 = blockIdx.x * 128;
    int bm = blockIdx.y, b = bm / 3, m = bm % 3;
    const float* in = (m == 0 ? x : ctx) + (size_t)b * CCH * HWN;
    __nv_bfloat16* out = (m == 0 ? &g_q[b][0][0] : m == 1 ? &g_k[b][0][0] : &g_v[b][0][0]);

    {
        int o = tid >> 1, part = (tid & 1) * 64;
        const uint16_t* src = (const uint16_t*)&g_effWh[b][m][o][part];
#pragma unroll
        for (int i = 0; i < 8; i++)
            *(uint4*)&Ws[o * WST + part + i * 8] = *(const uint4*)(src + i * 8);
    }
    __syncthreads();

    int o0 = warp * 16;
    uint32_t af[8][4];
#pragma unroll
    for (int kt = 0; kt < 8; kt++) {
        af[kt][0] = *(uint32_t*)&Ws[(o0 + l4) * WST + kt * 16 + k2];
        af[kt][1] = *(uint32_t*)&Ws[(o0 + l4 + 8) * WST + kt * 16 + k2];
        af[kt][2] = *(uint32_t*)&Ws[(o0 + l4) * WST + kt * 16 + k2 + 8];
        af[kt][3] = *(uint32_t*)&Ws[(o0 + l4 + 8) * WST + kt * 16 + k2 + 8];
    }

    float acc[16][4] = {};
    uint32_t xbase = smem_u32(Xs);

    for (int c4 = 0; c4 < 4; c4++) {
        int c = tid >> 3, seg = (tid & 7) * 16;
        const float* src = in + (size_t)(c4 * 32 + c) * HWN + s0 + seg;
        float4 f0 = *(const float4*)(src);
        float4 f1 = *(const float4*)(src + 4);
        float4 f2 = *(const float4*)(src + 8);
        float4 f3 = *(const float4*)(src + 12);
        uint32_t p[8];
        PACK_BF2(p[0], f0.x, f0.y); PACK_BF2(p[1], f0.z, f0.w);
        PACK_BF2(p[2], f1.x, f1.y); PACK_BF2(p[3], f1.z, f1.w);
        PACK_BF2(p[4], f2.x, f2.y); PACK_BF2(p[5], f2.z, f2.w);
        PACK_BF2(p[6], f3.x, f3.y); PACK_BF2(p[7], f3.z, f3.w);
        __syncthreads();
        *(uint4*)&Xs[c * XST + seg]     = make_uint4(p[0], p[1], p[2], p[3]);
        *(uint4*)&Xs[c * XST + seg + 8] = make_uint4(p[4], p[5], p[6], p[7]);
        __syncthreads();

#pragma unroll
        for (int kt = 0; kt < 2; kt++) {
#pragma unroll
            for (int pp = 0; pp < 8; pp++) {
                int c_row = kt * 16 + (mid & 1) * 8 + rr;
                int s_col = pp * 16 + (mid >> 1) * 8;
                uint32_t bf[4];
                LDSM_X4T(bf, xbase + (uint32_t)(c_row * XST + s_col) * 2u);
                mma16816(acc[2 * pp],     af[c4 * 2 + kt], bf[0], bf[1]);
                mma16816(acc[2 * pp + 1], af[c4 * 2 + kt], bf[2], bf[3]);
            }
        }
    }

    float b0 = g_effB[b][m][o0 + l4];
    float b1 = g_effB[b][m][o0 + l4 + 8];
#pragma unroll
    for (int nt = 0; nt < 16; nt++) {
        int s = s0 + nt * 8 + k2;
        uint32_t lo, hi;
        PACK_BF2(lo, acc[nt][0] + b0, acc[nt][1] + b0);
        PACK_BF2(hi, acc[nt][2] + b1, acc[nt][3] + b1);
        *(uint32_t*)&out[(size_t)(o0 + l4) * HWN + s]     = lo;
        *(uint32_t*)&out[(size_t)(o0 + l4 + 8) * HWN + s] = hi;
    }
}

// =================== flash attention, split-KV x2 ===================
#define AST 136
#define TBUF (32 * AST * 2)

__global__ void __launch_bounds__(256) attn_mma_kernel() {
    __shared__ __align__(16) uint16_t Qs[32 * AST];
    __shared__ __align__(16) uint16_t Ks[2][32 * AST];
    __shared__ __align__(16) uint16_t Vs[2][32 * AST];

    int tid = threadIdx.x, warp = tid >> 5, lane = tid & 31;
    int l4 = lane >> 2, mid = lane >> 3, rr = lane & 7;
    int dt = blockIdx.x, bh = blockIdx.y, sp = blockIdx.z;
    int b = bh >> 2, h = bh & 3;
    int d0 = dt * 128, r0 = warp * 16;

    const uint16_t* Qg = (const uint16_t*)&g_q[b][h * HD][0];
    const uint16_t* Kg = (const uint16_t*)&g_k[b][h * HD][0];
    const uint16_t* Vg = (const uint16_t*)&g_v[b][h * HD][0];

    uint32_t kbase = smem_u32(Ks);
    uint32_t vbase = smem_u32(Vs);
    int sc = tid >> 3, sseg = (tid & 7) * 16;
    int ebase = sp * 2048;

    {
        const uint16_t* src = Qg + (size_t)sc * HWN + d0 + sseg;
        *(uint4*)&Qs[sc * AST + sseg]     = *(const uint4*)(src);
        *(uint4*)&Qs[sc * AST + sseg + 8] = *(const uint4*)(src + 8);
    }
    __syncthreads();
    uint32_t qf[2][4];
    {
        uint32_t qb = smem_u32(Qs);
#pragma unroll
        for (int kt = 0; kt < 2; kt++) {
            int c_row = kt * 16 + (mid >> 1) * 8 + rr;
            int m_col = r0 + (mid & 1) * 8;
            LDSM_X4T(qf[kt], qb + (uint32_t)(c_row * AST + m_col) * 2u);
        }
    }
    __syncthreads();

    {
        uint32_t kd = kbase + (uint32_t)(sc * AST + sseg) * 2u;
        uint32_t vd = vbase + (uint32_t)(sc * AST + sseg) * 2u;
        cp16(kd,      Kg + (size_t)sc * HWN + ebase + sseg);
        cp16(kd + 16, Kg + (size_t)sc * HWN + ebase + sseg + 8);
        cp16(vd,      Vg + (size_t)sc * HWN + ebase + sseg);
        cp16(vd + 16, Vg + (size_t)sc * HWN + ebase + sseg + 8);
    }
    CP_COMMIT();

    float O[4][4] = {};
    float ls0 = 0.f, ls1 = 0.f;

    for (int it = 0; it < 16; it++) {
        int buf = it & 1;
        CP_WAIT0();
        __syncthreads();
        if (it + 1 < 16) {
            int e1 = ebase + (it + 1) * 128;
            uint32_t kd = kbase + (uint32_t)(buf ^ 1) * TBUF + (uint32_t)(sc * AST + sseg) * 2u;
            uint32_t vd = vbase + (uint32_t)(buf ^ 1) * TBUF + (uint32_t)(sc * AST + sseg) * 2u;
            cp16(kd,      Kg + (size_t)sc * HWN + e1 + sseg);
            cp16(kd + 16, Kg + (size_t)sc * HWN + e1 + sseg + 8);
            cp16(vd,      Vg + (size_t)sc * HWN + e1 + sseg);
            cp16(vd + 16, Vg + (size_t)sc * HWN + e1 + sseg + 8);
        }
        CP_COMMIT();

        // ---- MMA1: S[16 x 128] ----
        float S[16][4];
#pragma unroll
        for (int nt = 0; nt < 16; nt++) { S[nt][0] = S[nt][1] = S[nt][2] = S[nt][3] = 0.f; }
#pragma unroll
        for (int kt = 0; kt < 2; kt++) {
#pragma unroll
            for (int pp = 0; pp < 8; pp++) {
                int c_row = kt * 16 + (mid & 1) * 8 + rr;
                int n_col = pp * 16 + (mid >> 1) * 8;
                uint32_t bf[4];
                LDSM_X4T(bf, kbase + (uint32_t)buf * TBUF + (uint32_t)(c_row * AST + n_col) * 2u);
                mma16816(S[2 * pp],     qf[kt], bf[0], bf[1]);
                mma16816(S[2 * pp + 1], qf[kt], bf[2], bf[3]);
            }
        }

        // ---- softmax: P = 2^S (log2e folded into Wq) ----
        uint32_t pf[8][4];
#pragma unroll
        for (int t = 0; t < 8; t++) {
            float e00, e01, e02, e03, e10, e11, e12, e13;
            EX2(e00, S[2 * t][0]);     EX2(e01, S[2 * t][1]);
            EX2(e02, S[2 * t][2]);     EX2(e03, S[2 * t][3]);
            EX2(e10, S[2 * t + 1][0]); EX2(e11, S[2 * t + 1][1]);
            EX2(e12, S[2 * t + 1][2]); EX2(e13, S[2 * t + 1][3]);
            ls0 += (e00 + e01) + (e10 + e11);
            ls1 += (e02 + e03) + (e12 + e13);
            PACK_BF2(pf[t][0], e00, e01);
            PACK_BF2(pf[t][1], e02, e03);
            PACK_BF2(pf[t][2], e10, e11);
            PACK_BF2(pf[t][3], e12, e13);
        }

        // ---- MMA2: O[16 x 32] += P V^T ----
#pragma unroll
        for (int kt = 0; kt < 8; kt++) {
#pragma unroll
            for (int pp = 0; pp < 2; pp++) {
                int n_row = pp * 16 + (mid >> 1) * 8 + rr;
                int koff  = kt * 16 + (mid & 1) * 8;
                uint32_t bf[4];
                LDSM_X4(bf, vbase + (uint32_t)buf * TBUF + (uint32_t)(n_row * AST + koff) * 2u);
                mma16816(O[2 * pp],     pf[kt], bf[0], bf[1]);
                mma16816(O[2 * pp + 1], pf[kt], bf[2], bf[3]);
            }
        }
    }

    // ---- epilogue: write unnormalized partials + row sums ----
    ls0 += __shfl_xor_sync(0xffffffffu, ls0, 1);
    ls0 += __shfl_xor_sync(0xffffffffu, ls0, 2);
    ls1 += __shfl_xor_sync(0xffffffffu, ls1, 1);
    ls1 += __shfl_xor_sync(0xffffffffu, ls1, 2);
    int k2 = (lane & 3) * 2;
    if ((lane & 3) == 0) {
        g_pl[sp][bh][d0 + r0 + l4]     = ls0;
        g_pl[sp][bh][d0 + r0 + l4 + 8] = ls1;
    }
#pragma unroll
    for (int nt = 0; nt < 4; nt++) {
        int ch = nt * 8 + k2;
        *(float2*)&g_po[sp][bh][dt][r0 + l4][ch]     = make_float2(O[nt][0], O[nt][1]);
        *(float2*)&g_po[sp][bh][dt][r0 + l4 + 8][ch] = make_float2(O[nt][2], O[nt][3]);
    }
}

// =================== combine splits -> bf16 g_ao ===================
__global__ void __launch_bounds__(256) combine_kernel() {
    int dt = blockIdx.x, bh = blockIdx.y;
    int b = bh >> 2, h = bh & 3;
    int tid = threadIdx.x;
    int ch8 = tid >> 5, rl = tid & 31;
#pragma unroll
    for (int r4 = 0; r4 < 4; r4++) {
        int row = rl + r4 * 32;
        float l = g_pl[0][bh][dt * 128 + row] + g_pl[1][bh][dt * 128 + row];
        float inv = __frcp_rn(l);
#pragma unroll
        for (int i = 0; i < 4; i++) {
            int cc = ch8 + i * 8;
            float v = g_po[0][bh][dt][row][cc] + g_po[1][bh][dt][row][cc];
            g_ao[b][h * HD + cc][dt * 128 + row] = __float2bfloat16(v * inv);
        }
    }
}

// =================== out projection on HMMA + residual ===================
__global__ void __launch_bounds__(256) out_proj_mma_kernel(const float* __restrict__ x,
                                                           const float* __restrict__ bout,
                                                           const float* __restrict__ alpha,
                                                           float* __restrict__ y) {
    __shared__ __align__(16) uint16_t Ws[128 * WST];
    __shared__ __align__(16) uint16_t Xs[32 * XST];

    int tid = threadIdx.x, warp = tid >> 5, lane = tid & 31;
    int l4 = lane >> 2, k2 = (lane & 3) * 2;
    int mid = lane >> 3, rr = lane & 7;
    int s0 = blockIdx.x * 128, b = blockIdx.y;
    const uint16_t* in = (const uint16_t*)&g_ao[b][0][0];

    {
        int o = tid >> 1, part = (tid & 1) * 64;
        const uint16_t* src = (const uint16_t*)&g_Wouth[o][part];
#pragma unroll
        for (int i = 0; i < 8; i++)
            *(uint4*)&Ws[o * WST + part + i * 8] = *(const uint4*)(src + i * 8);
    }
    __syncthreads();

    int o0 = warp * 16;
    uint32_t af[8][4];
#pragma unroll
    for (int kt = 0; kt < 8; kt++) {
        af[kt][0] = *(uint32_t*)&Ws[(o0 + l4) * WST + kt * 16 + k2];
        af[kt][1] = *(uint32_t*)&Ws[(o0 + l4 + 8) * WST + kt * 16 + k2];
        af[kt][2] = *(uint32_t*)&Ws[(o0 + l4) * WST + kt * 16 + k2 + 8];
        af[kt][3] = *(uint32_t*)&Ws[(o0 + l4 + 8) * WST + kt * 16 + k2 + 8];
    }

    float acc[16][4] = {};
    uint32_t xbase = smem_u32(Xs);

    for (int c4 = 0; c4 < 4; c4++) {
        int c = tid >> 3, seg = (tid & 7) * 16;
        const uint16_t* src = in + (size_t)(c4 * 32 + c) * HWN + s0 + seg;
        uint4 v0 = *(const uint4*)(src);
        uint4 v1 = *(const uint4*)(src + 8);
        __syncthreads();
        *(uint4*)&Xs[c * XST + seg]     = v0;
        *(uint4*)&Xs[c * XST + seg + 8] = v1;
        __syncthreads();

#pragma unroll
        for (int kt = 0; kt < 2; kt++) {
#pragma unroll
            for (int pp = 0; pp < 8; pp++) {
                int c_row = kt * 16 + (mid & 1) * 8 + rr;
                int s_col = pp * 16 + (mid >> 1) * 8;
                uint32_t bf[4];
                LDSM_X4T(bf, xbase + (uint32_t)(c_row * XST + s_col) * 2u);
                mma16816(acc[2 * pp],     af[c4 * 2 + kt], bf[0], bf[1]);
                mma16816(acc[2 * pp + 1], af[c4 * 2 + kt], bf[2], bf[3]);
            }
        }
    }

    float a = *alpha;
    float b0 = bout[o0 + l4], b1 = bout[o0 + l4 + 8];
    size_t base0 = ((size_t)b * CCH + o0 + l4) * HWN;
    size_t base1 = ((size_t)b * CCH + o0 + l4 + 8) * HWN;
#pragma unroll
    for (int nt = 0; nt < 16; nt++) {
        int s = s0 + nt * 8 + k2;
        float2 x0 = *(const float2*)(x + base0 + s);
        float2 x1 = *(const float2*)(x + base1 + s);
        float2 r0, r1;
        r0.x = x0.x + a * (acc[nt][0] + b0);
        r0.y = x0.y + a * (acc[nt][1] + b0);
        r1.x = x1.x + a * (acc[nt][2] + b1);
        r1.y = x1.y + a * (acc[nt][3] + b1);
        *(float2*)(y + base0 + s) = r0;
        *(float2*)(y + base1 + s) = r1;
    }
}

// =================== launch ===================
extern "C" void kernel_launch(void* const* d_in, const int* in_sizes, int n_in,
                              void* d_out, int out_size) {
    const float* x    = (const float*)d_in[0];
    const float* ctx  = (const float*)d_in[1];
    const float* gq   = (const float*)d_in[2];
    const float* bq   = (const float*)d_in[3];
    const float* gctx = (const float*)d_in[4];
    const float* bctx = (const float*)d_in[5];
    const float* Wq   = (const float*)d_in[6];
    const float* Wk   = (const float*)d_in[7];
    const float* Wv   = (const float*)d_in[8];
    const float* Wout = (const float*)d_in[9];
    const float* bout = (const float*)d_in[10];
    const float* alpha= (const float*)d_in[11];
    float* y = (float*)d_out;

    gn_stats_kernel<<<dim3(32, NB, 2), 256>>>(x, ctx, gq, bq, gctx, bctx);
    eff_weights_kernel<<<dim3(CCH, 4, NB), 128>>>(Wq, Wk, Wv, Wout);
    qkv_mma_kernel<<<dim3(32, NB * 3), 256>>>(x, ctx);
    attn_mma_kernel<<<dim3(32, NB * NHEADS, 2), 256>>>();
    combine_kernel<<<dim3(32, NB * NHEADS), 256>>>();
    out_proj_mma_kernel<<<dim3(32, NB), 256>>>(x, bout, alpha, y);
}